// round 13
// baseline (speedup 1.0000x reference)
#include <cuda_runtime.h>
#include <cuda_bf16.h>
#include <math.h>
#include <stdint.h>

#define BATCH 4
#define CH 64
#define OC 64
#define HH 128
#define WW 128
#define HW (HH*WW)
#define PIX (BATCH*HW)
#define K2 9
#define KKD 576            // K2*CH

// -------- device scratch (no allocations allowed) --------
__device__ float g_xn[PIX*CH];            // x in NHWC fp32: [b][h][w][c]
__device__ unsigned g_xbf_hi[PIX*32];     // x bf16 hi plane: [pix][cpair]
__device__ unsigned g_xbf_lo[PIX*32];     // x bf16 lo plane
__device__ float g_offs[PIX*18];          // offsets: [pix][18]
__device__ uint4 g_wfragH[K2*512];        // deform B hi frags: [k][kt*4+ng][lane]
__device__ uint4 g_wfragL[K2*512];        // deform B lo frags
__device__ uint2 g_wofH[K2*384];          // offconv B hi frags: [k][kt*3+ng][lane]
__device__ uint2 g_wofL[K2*384];          // offconv B lo frags
__device__ float4 g_pw[PIX*K2];           // bilinear weights (validity folded)
__device__ int4  g_po[PIX*K2];            // per-corner clamped byte offsets

// single dynamic-shared symbol shared by all kernels
extern __shared__ char smraw[];

// pack two fp32 -> bf16x2 (first arg -> lower 16 bits)
__device__ __forceinline__ unsigned pk_bf16x2(float lo, float hi) {
    unsigned r;
    asm("cvt.rn.bf16x2.f32 %0, %1, %2;" : "=r"(r) : "f"(hi), "f"(lo));
    return r;
}
__device__ __forceinline__ uint32_t smem_u32(const void* p) {
    uint32_t a;
    asm("{ .reg .u64 t; cvta.to.shared.u64 t, %1; cvt.u32.u64 %0, t; }" : "=r"(a) : "l"(p));
    return a;
}
__device__ __forceinline__ void ldsm4(uint32_t* r, uint32_t addr) {
    asm volatile("ldmatrix.sync.aligned.m8n8.x4.shared.b16 {%0,%1,%2,%3}, [%4];"
        : "=r"(r[0]), "=r"(r[1]), "=r"(r[2]), "=r"(r[3]) : "r"(addr));
}
__device__ __forceinline__ void mma16816(float* c, const uint32_t* a, uint32_t b0, uint32_t b1) {
    asm volatile("mma.sync.aligned.m16n8k16.row.col.f32.bf16.bf16.f32 "
        "{%0,%1,%2,%3}, {%4,%5,%6,%7}, {%8,%9}, {%0,%1,%2,%3};"
        : "+f"(c[0]), "+f"(c[1]), "+f"(c[2]), "+f"(c[3])
        : "r"(a[0]), "r"(a[1]), "r"(a[2]), "r"(a[3]), "r"(b0), "r"(b1));
}

// ============ kernel 1: transpose + bf16 planes + (folded) weight reorder ============
__global__ void k_transpose(const float* __restrict__ x,
                            const float* __restrict__ w_off,
                            const float* __restrict__ w_dcn) {
    __shared__ float tile[32][33];
    int bh = blockIdx.z;                 // b*128 + h
    int c0 = blockIdx.y * 32;
    int w0 = blockIdx.x * 32;
    int b = bh >> 7, h = bh & 127;
    int tx = threadIdx.x, ty = threadIdx.y;
#pragma unroll
    for (int i = 0; i < 4; i++) {
        int c = c0 + ty + i*8;
        tile[ty + i*8][tx] = x[((b*CH + c)*HH + h)*WW + w0 + tx];
    }
    __syncthreads();
#pragma unroll
    for (int i = 0; i < 4; i++) {
        int w = w0 + ty + i*8;
        g_xn[(bh*WW + w)*CH + c0 + tx] = tile[tx][ty + i*8];
    }
    if (tx < 16) {
#pragma unroll
        for (int i = 0; i < 4; i++) {
            int wi = ty + i*8;
            int w = w0 + wi;
            float v0 = tile[2*tx][wi];
            float v1 = tile[2*tx + 1][wi];
            unsigned h2 = pk_bf16x2(v0, v1);
            float h0 = __uint_as_float(h2 << 16);
            float h1 = __uint_as_float(h2 & 0xFFFF0000u);
            unsigned l2 = pk_bf16x2(v0 - h0, v1 - h1);
            int idx = (bh*WW + w)*32 + (c0 >> 1) + tx;
            g_xbf_hi[idx] = h2;
            g_xbf_lo[idx] = l2;
        }
    }

    // ---- folded weight reorder (sub-grid slice: x==0 && y==0 -> 512 blocks) ----
    if (blockIdx.x == 0 && blockIdx.y == 0) {
        int t = blockIdx.z*256 + ty*32 + tx;
        int stride = 512*256;
        unsigned hw_, lw_;
        float a0, a1, h0, h1;
#define MKW(SRC, KK, NN, KP, HRES, LRES) \
        a0 = SRC[(NN)*KKD + (KK)*K2 + KP]; \
        a1 = SRC[(NN)*KKD + (KK+1)*K2 + KP]; \
        hw_ = pk_bf16x2(a0, a1); \
        h0 = __uint_as_float(hw_ << 16); \
        h1 = __uint_as_float(hw_ & 0xFFFF0000u); \
        lw_ = pk_bf16x2(a0 - h0, a1 - h1); \
        HRES = hw_; LRES = lw_;
        for (int idx = t; idx < K2*512; idx += stride) {
            int kpos = idx / 512;
            int rem = idx & 511;
            int tl = rem >> 5;        // kt*4 + ng
            int lane = rem & 31;
            int kt = tl >> 2, ng = tl & 3;
            int n0 = ng*16 + (lane >> 2);
            int k0 = kt*16 + (lane & 3)*2;
            uint4 hi, lo;
            MKW(w_dcn, k0,     n0,     kpos, hi.x, lo.x)
            MKW(w_dcn, k0 + 8, n0,     kpos, hi.y, lo.y)
            MKW(w_dcn, k0,     n0 + 8, kpos, hi.z, lo.z)
            MKW(w_dcn, k0 + 8, n0 + 8, kpos, hi.w, lo.w)
            g_wfragH[idx] = hi;
            g_wfragL[idx] = lo;
        }
        for (int idx = t; idx < K2*384; idx += stride) {
            int kpos = idx / 384;
            int rem = idx - kpos*384;
            int tl = rem >> 5;        // kt*3 + ng
            int lane = rem & 31;
            int kt = tl / 3, ng = tl - kt*3;
            int n0 = ng*8 + (lane >> 2);
            int k0 = kt*16 + (lane & 3)*2;
            uint2 hi, lo;
            if (n0 < 18) {
                MKW(w_off, k0,     n0, kpos, hi.x, lo.x)
                MKW(w_off, k0 + 8, n0, kpos, hi.y, lo.y)
            } else {
                hi.x = hi.y = lo.x = lo.y = 0u;
            }
            g_wofH[idx] = hi;
            g_wofL[idx] = lo;
        }
#undef MKW
    }
}

// ============ kernel 2: offset conv via mma.sync (C=64 -> 18, 3x3, pad1) ============
#define OSA_HI 0
#define OSA_LO 16384
#define SMEM_OFF 32768

__global__ void __launch_bounds__(256)
k_offconv(const float* __restrict__ b_off) {
    char* sm = smraw;
    uint32_t sb = smem_u32(sm);
    int t = threadIdx.x;
    int lane = t & 31, warp = t >> 5;
    int blk = blockIdx.x;               // b*128 + h
    int b = blk >> 7, h = blk & 127;
    int pix0 = blk * WW;

    float acc[3][4];
#pragma unroll
    for (int i = 0; i < 3; i++)
#pragma unroll
        for (int j = 0; j < 4; j++) acc[i][j] = 0.f;

    int ltile = lane >> 3, lrow = lane & 7;
    int a_r = (ltile & 1)*8 + lrow;
    int a_gr = warp*16 + a_r;
    int a_cpar = ltile >> 1;
    uint32_t a_base = sb + a_gr*128;

    for (int k = 0; k < K2; k++) {
        int ky = k / 3, kx = k - ky*3;
        int y = h + ky - 1;
        bool vy = (unsigned)y < HH;
        const unsigned* hp = &g_xbf_hi[((size_t)(b*HH + (vy ? y : 0)))*WW*32];
        const unsigned* lp = &g_xbf_lo[((size_t)(b*HH + (vy ? y : 0)))*WW*32];
#pragma unroll 8
        for (int j = 0; j < 16; j++) {
            int p = warp*16 + j;
            int xx = p + kx - 1;
            bool v = vy && ((unsigned)xx < WW);
            unsigned h2 = v ? hp[xx*32 + lane] : 0u;
            unsigned l2 = v ? lp[xx*32 + lane] : 0u;
            unsigned off = p*128 + ((((lane >> 2) ^ (j & 7)) << 4) | ((lane & 3) << 2));
            *(unsigned*)(sm + OSA_HI + off) = h2;
            *(unsigned*)(sm + OSA_LO + off) = l2;
        }
        __syncwarp();

        const uint2* bfH = &g_wofH[k*384 + lane];
        const uint2* bfL = &g_wofL[k*384 + lane];
#pragma unroll
        for (int kt = 0; kt < 4; kt++) {
            uint32_t aH[4], aL[4];
            int chunkk = 2*kt + a_cpar;
            uint32_t addr = a_base + ((chunkk ^ (a_gr & 7)) << 4);
            ldsm4(aH, addr + OSA_HI);
            ldsm4(aL, addr + OSA_LO);
#pragma unroll
            for (int ng = 0; ng < 3; ng++) {
                uint2 BH = bfH[(kt*3 + ng)*32];
                uint2 BL = bfL[(kt*3 + ng)*32];
                mma16816(acc[ng], aH, BH.x, BH.y);
                mma16816(acc[ng], aL, BH.x, BH.y);
                mma16816(acc[ng], aH, BL.x, BL.y);
            }
        }
        __syncwarp();
    }

    int r0 = lane >> 2;
    int cq = (lane & 3)*2;
    int p0 = pix0 + warp*16 + r0;
    int p1 = p0 + 8;
#pragma unroll
    for (int ng = 0; ng < 3; ng++) {
        int col = ng*8 + cq;
        if (col < 18) {
            float bi0 = b_off[col], bi1 = b_off[col+1];
            g_offs[(size_t)p0*18 + col]     = acc[ng][0] + bi0;
            g_offs[(size_t)p0*18 + col + 1] = acc[ng][1] + bi1;
            g_offs[(size_t)p1*18 + col]     = acc[ng][2] + bi0;
            g_offs[(size_t)p1*18 + col + 1] = acc[ng][3] + bi1;
        }
    }
}

// ============ kernel 3: bilinear precompute (coalesced streaming) ============
__global__ void k_precomp() {
    int idx = blockIdx.x*blockDim.x + threadIdx.x;
    if (idx >= PIX*K2) return;
    int pix = idx / K2, k = idx - pix*K2;
    int hw = pix & (HW-1);
    int h = hw >> 7, w = hw & 127;
    float dy = g_offs[pix*18 + 2*k];
    float dx = g_offs[pix*18 + 2*k + 1];
    int ky = k / 3, kx = k - ky*3;
    float py = (float)(h + ky - 1) + dy;
    float px = (float)(w + kx - 1) + dx;
    float y0f = floorf(py), x0f = floorf(px);
    float wy = py - y0f, wx = px - x0f;
    int y0 = (int)y0f, x0 = (int)x0f;
    bool vy0 = (y0 >= 0) && (y0 < HH);
    bool vy1 = (y0 >= -1) && (y0 < HH-1);
    bool vx0 = (x0 >= 0) && (x0 < WW);
    bool vx1 = (x0 >= -1) && (x0 < WW-1);
    int iy0 = min(max(y0, 0), HH-1), iy1 = min(max(y0+1, 0), HH-1);
    int ix0 = min(max(x0, 0), WW-1), ix1 = min(max(x0+1, 0), WW-1);
    float4 wv;
    wv.x = (vy0 && vx0) ? (1.f-wy)*(1.f-wx) : 0.f;
    wv.y = (vy0 && vx1) ? (1.f-wy)*wx       : 0.f;
    wv.z = (vy1 && vx0) ? wy*(1.f-wx)       : 0.f;
    wv.w = (vy1 && vx1) ? wy*wx             : 0.f;
    int4 ov;
    ov.x = (iy0*WW + ix0)*CH*4;
    ov.y = (iy0*WW + ix1)*CH*4;
    ov.z = (iy1*WW + ix0)*CH*4;
    ov.w = (iy1*WW + ix1)*CH*4;
    g_pw[idx] = wv;
    g_po[idx] = ov;
}

// ============ kernel 4: deformable conv v12 (v9 + paired float4 corner loads) ============
// Block: 128 threads = 4 warps, 64 pixels, 64 oc. Gather: per 8-px chunk,
// paired LDG.128 (lanes 0-15 = pixel 2i, lanes 16-31 = pixel 2i+1, 4 ch each),
// 2-pass corners. Halves corner LDG / shuffle / STS instruction counts vs v9.
#define SMA_HI 0
#define SMA_LO 8192
#define SMEM_DEF 16384

__global__ void __launch_bounds__(128, 6)
k_deform(const float* __restrict__ b_dcn, float* __restrict__ out) {
    char* sm = smraw;
    uint32_t sb = smem_u32(sm);
    int t = threadIdx.x;
    int lane = t & 31, warp = t >> 5;   // warp in [0,4)
    int blk = blockIdx.x;               // 0..1023
    int pix0 = blk * 64;
    int b = pix0 >> 14;
    int h = (pix0 & (HW-1)) >> 7;
    const char* xc = (const char*)&g_xn[(size_t)b * (HW*CH)];
    int m = lane & 15;                  // channel-quad index / pw-po holder index
    int lc4 = m * 16;                   // byte offset: 4 channels
    int psel = lane >> 4;               // which pixel of the pair

    float acc[8][4];
#pragma unroll
    for (int i = 0; i < 8; i++)
#pragma unroll
        for (int j = 0; j < 4; j++) acc[i][j] = 0.f;

    int ltile = lane >> 3, lrow = lane & 7;
    int a_r = (ltile & 1)*8 + lrow;
    int a_gr = warp*16 + a_r;           // local A row (0..63)
    int a_cpar = ltile >> 1;
    uint32_t a_base = sb + a_gr*128;

    // lane m holds pixel (warp*16 + m)'s pw/po
    size_t pp = (size_t)(pix0 + warp*16 + m)*K2;
    float4 pw_r = g_pw[pp];
    int4   po_r = g_po[pp];

    for (int k = 0; k < K2; k++) {
        // ---- gather 16 warp-local pixels: 2 chunks of 8 px (4 pairs each) ----
#pragma unroll
        for (int ch_ = 0; ch_ < 2; ch_++) {
            float4 part[4];
            {   // pass 1: top corners
                float4 c00[4], c01[4];
#pragma unroll
                for (int i = 0; i < 4; i++) {
                    int j = ch_*8 + 2*i + psel;
                    int o0 = __shfl_sync(0xffffffffu, po_r.x, j);
                    int o1 = __shfl_sync(0xffffffffu, po_r.y, j);
                    c00[i] = *(const float4*)(xc + o0 + lc4);
                    c01[i] = *(const float4*)(xc + o1 + lc4);
                }
#pragma unroll
                for (int i = 0; i < 4; i++) {
                    int j = ch_*8 + 2*i + psel;
                    float w0_ = __shfl_sync(0xffffffffu, pw_r.x, j);
                    float w1_ = __shfl_sync(0xffffffffu, pw_r.y, j);
                    part[i].x = w0_*c00[i].x + w1_*c01[i].x;
                    part[i].y = w0_*c00[i].y + w1_*c01[i].y;
                    part[i].z = w0_*c00[i].z + w1_*c01[i].z;
                    part[i].w = w0_*c00[i].w + w1_*c01[i].w;
                }
            }
            {   // pass 2: bottom corners + convert + store
                float4 c10[4], c11[4];
#pragma unroll
                for (int i = 0; i < 4; i++) {
                    int j = ch_*8 + 2*i + psel;
                    int o2 = __shfl_sync(0xffffffffu, po_r.z, j);
                    int o3 = __shfl_sync(0xffffffffu, po_r.w, j);
                    c10[i] = *(const float4*)(xc + o2 + lc4);
                    c11[i] = *(const float4*)(xc + o3 + lc4);
                }
#pragma unroll
                for (int i = 0; i < 4; i++) {
                    int j = ch_*8 + 2*i + psel;
                    float w2_ = __shfl_sync(0xffffffffu, pw_r.z, j);
                    float w3_ = __shfl_sync(0xffffffffu, pw_r.w, j);
                    float4 r;
                    r.x = part[i].x + w2_*c10[i].x + w3_*c11[i].x;
                    r.y = part[i].y + w2_*c10[i].y + w3_*c11[i].y;
                    r.z = part[i].z + w2_*c10[i].z + w3_*c11[i].z;
                    r.w = part[i].w + w2_*c10[i].w + w3_*c11[i].w;
                    unsigned h2a = pk_bf16x2(r.x, r.y);
                    unsigned h2b = pk_bf16x2(r.z, r.w);
                    float hx = __uint_as_float(h2a << 16);
                    float hy = __uint_as_float(h2a & 0xFFFF0000u);
                    float hz = __uint_as_float(h2b << 16);
                    float hw_ = __uint_as_float(h2b & 0xFFFF0000u);
                    unsigned l2a = pk_bf16x2(r.x - hx, r.y - hy);
                    unsigned l2b = pk_bf16x2(r.z - hz, r.w - hw_);
                    int p = warp*16 + ch_*8 + 2*i + psel;
                    unsigned off = p*128 + ((((m >> 1) ^ (p & 7)) << 4) | (((2*m) & 3) << 2));
                    *(uint2*)(sm + SMA_HI + off) = make_uint2(h2a, h2b);
                    *(uint2*)(sm + SMA_LO + off) = make_uint2(l2a, l2b);
                }
            }
        }
        __syncwarp();

        if (k < K2-1) {
            pw_r = g_pw[pp + k + 1];
            po_r = g_po[pp + k + 1];
        }

        // ---- GEMM: m16 x n64 x k64, 3-term bf16 split ----
        const uint4* bfH = &g_wfragH[k*512 + lane];
        const uint4* bfL = &g_wfragL[k*512 + lane];
#pragma unroll
        for (int kt = 0; kt < 4; kt++) {
            uint32_t aH[4], aL[4];
            int chunkk = 2*kt + a_cpar;
            uint32_t addr = a_base + ((chunkk ^ (a_gr & 7)) << 4);
            ldsm4(aH, addr + SMA_HI);
            ldsm4(aL, addr + SMA_LO);
#pragma unroll
            for (int ng = 0; ng < 4; ng++) {
                uint4 BH = bfH[(kt*4 + ng)*32];
                uint4 BL = bfL[(kt*4 + ng)*32];
                mma16816(acc[2*ng],   aH, BH.x, BH.y);
                mma16816(acc[2*ng],   aL, BH.x, BH.y);
                mma16816(acc[2*ng],   aH, BL.x, BL.y);
                mma16816(acc[2*ng+1], aH, BH.z, BH.w);
                mma16816(acc[2*ng+1], aL, BH.z, BH.w);
                mma16816(acc[2*ng+1], aH, BL.z, BL.w);
            }
        }
        __syncwarp();
    }

    // epilogue: write fragments to NCHW out
    int r0 = lane >> 2;
    int cq = (lane & 3)*2;
    int w0 = (pix0 & 127) + warp*16 + r0;
    size_t obase = (size_t)b*OC*HW + (size_t)h*WW;
#pragma unroll
    for (int nt = 0; nt < 8; nt++) {
        int oc = nt*8 + cq;
        float bias0 = b_dcn[oc];
        float bias1 = b_dcn[oc+1];
        float* o0 = &out[obase + (size_t)oc*HW];
        float* o1 = &out[obase + (size_t)(oc+1)*HW];
        o0[w0]     = acc[nt][0] + bias0;
        o1[w0]     = acc[nt][1] + bias1;
        o0[w0 + 8] = acc[nt][2] + bias0;
        o1[w0 + 8] = acc[nt][3] + bias1;
    }
}

// ============ launch ============
extern "C" void kernel_launch(void* const* d_in, const int* in_sizes, int n_in,
                              void* d_out, int out_size) {
    const float* x     = (const float*)d_in[0];
    const float* w_off = (const float*)d_in[1];
    const float* b_off = (const float*)d_in[2];
    const float* w_dcn = (const float*)d_in[3];
    const float* b_dcn = (const float*)d_in[4];
    float* out = (float*)d_out;

    cudaFuncSetAttribute(k_offconv, cudaFuncAttributeMaxDynamicSharedMemorySize, SMEM_OFF);
    cudaFuncSetAttribute(k_deform,  cudaFuncAttributeMaxDynamicSharedMemorySize, SMEM_DEF);

    k_transpose<<<dim3(WW/32, CH/32, BATCH*HH), dim3(32,8)>>>(x, w_off, w_dcn);
    k_offconv<<<BATCH*HH, 256, SMEM_OFF>>>(b_off);
    k_precomp<<<(PIX*K2 + 255)/256, 256>>>();
    k_deform<<<PIX/64, 128, SMEM_DEF>>>(b_dcn, out);
}

// round 14
// speedup vs baseline: 1.2583x; 1.2583x over previous
#include <cuda_runtime.h>
#include <cuda_bf16.h>
#include <math.h>
#include <stdint.h>

#define BATCH 4
#define CH 64
#define OC 64
#define HH 128
#define WW 128
#define HW (HH*WW)
#define PIX (BATCH*HW)
#define K2 9
#define KKD 576            // K2*CH

// -------- device scratch (no allocations allowed) --------
__device__ float g_xn[PIX*CH];            // x in NHWC fp32: [b][h][w][c]
__device__ unsigned g_xbf_hi[PIX*32];     // x bf16 hi plane: [pix][cpair]
__device__ unsigned g_xbf_lo[PIX*32];     // x bf16 lo plane
__device__ float g_offs[PIX*18];          // offsets: [pix][18]
__device__ uint4 g_wfragH[K2*512];        // deform B hi frags: [k][kt*4+ng][lane]
__device__ uint4 g_wfragL[K2*512];        // deform B lo frags
__device__ uint2 g_wofH[K2*384];          // offconv B hi frags: [k][kt*3+ng][lane]
__device__ uint2 g_wofL[K2*384];          // offconv B lo frags
__device__ float4 g_pw[PIX*K2];           // bilinear weights (validity folded)
__device__ int4  g_po[PIX*K2];            // per-corner clamped byte offsets

// single dynamic-shared symbol shared by all kernels
extern __shared__ char smraw[];

// pack two fp32 -> bf16x2 (first arg -> lower 16 bits)
__device__ __forceinline__ unsigned pk_bf16x2(float lo, float hi) {
    unsigned r;
    asm("cvt.rn.bf16x2.f32 %0, %1, %2;" : "=r"(r) : "f"(hi), "f"(lo));
    return r;
}
__device__ __forceinline__ uint32_t smem_u32(const void* p) {
    uint32_t a;
    asm("{ .reg .u64 t; cvta.to.shared.u64 t, %1; cvt.u32.u64 %0, t; }" : "=r"(a) : "l"(p));
    return a;
}
__device__ __forceinline__ void ldsm4(uint32_t* r, uint32_t addr) {
    asm volatile("ldmatrix.sync.aligned.m8n8.x4.shared.b16 {%0,%1,%2,%3}, [%4];"
        : "=r"(r[0]), "=r"(r[1]), "=r"(r[2]), "=r"(r[3]) : "r"(addr));
}
__device__ __forceinline__ void mma16816(float* c, const uint32_t* a, uint32_t b0, uint32_t b1) {
    asm volatile("mma.sync.aligned.m16n8k16.row.col.f32.bf16.bf16.f32 "
        "{%0,%1,%2,%3}, {%4,%5,%6,%7}, {%8,%9}, {%0,%1,%2,%3};"
        : "+f"(c[0]), "+f"(c[1]), "+f"(c[2]), "+f"(c[3])
        : "r"(a[0]), "r"(a[1]), "r"(a[2]), "r"(a[3]), "r"(b0), "r"(b1));
}

// ============ kernel 1: transpose + bf16 planes + (folded) weight reorder ============
__global__ void k_transpose(const float* __restrict__ x,
                            const float* __restrict__ w_off,
                            const float* __restrict__ w_dcn) {
    __shared__ float tile[32][33];
    int bh = blockIdx.z;                 // b*128 + h
    int c0 = blockIdx.y * 32;
    int w0 = blockIdx.x * 32;
    int b = bh >> 7, h = bh & 127;
    int tx = threadIdx.x, ty = threadIdx.y;
#pragma unroll
    for (int i = 0; i < 4; i++) {
        int c = c0 + ty + i*8;
        tile[ty + i*8][tx] = x[((b*CH + c)*HH + h)*WW + w0 + tx];
    }
    __syncthreads();
#pragma unroll
    for (int i = 0; i < 4; i++) {
        int w = w0 + ty + i*8;
        g_xn[(bh*WW + w)*CH + c0 + tx] = tile[tx][ty + i*8];
    }
    if (tx < 16) {
#pragma unroll
        for (int i = 0; i < 4; i++) {
            int wi = ty + i*8;
            int w = w0 + wi;
            float v0 = tile[2*tx][wi];
            float v1 = tile[2*tx + 1][wi];
            unsigned h2 = pk_bf16x2(v0, v1);
            float h0 = __uint_as_float(h2 << 16);
            float h1 = __uint_as_float(h2 & 0xFFFF0000u);
            unsigned l2 = pk_bf16x2(v0 - h0, v1 - h1);
            int idx = (bh*WW + w)*32 + (c0 >> 1) + tx;
            g_xbf_hi[idx] = h2;
            g_xbf_lo[idx] = l2;
        }
    }

    // ---- folded weight reorder (sub-grid slice: x==0 && y==0 -> 512 blocks) ----
    if (blockIdx.x == 0 && blockIdx.y == 0) {
        int t = blockIdx.z*256 + ty*32 + tx;
        int stride = 512*256;
        unsigned hw_, lw_;
        float a0, a1, h0, h1;
#define MKW(SRC, KK, NN, KP, HRES, LRES) \
        a0 = SRC[(NN)*KKD + (KK)*K2 + KP]; \
        a1 = SRC[(NN)*KKD + (KK+1)*K2 + KP]; \
        hw_ = pk_bf16x2(a0, a1); \
        h0 = __uint_as_float(hw_ << 16); \
        h1 = __uint_as_float(hw_ & 0xFFFF0000u); \
        lw_ = pk_bf16x2(a0 - h0, a1 - h1); \
        HRES = hw_; LRES = lw_;
        for (int idx = t; idx < K2*512; idx += stride) {
            int kpos = idx / 512;
            int rem = idx & 511;
            int tl = rem >> 5;        // kt*4 + ng
            int lane = rem & 31;
            int kt = tl >> 2, ng = tl & 3;
            int n0 = ng*16 + (lane >> 2);
            int k0 = kt*16 + (lane & 3)*2;
            uint4 hi, lo;
            MKW(w_dcn, k0,     n0,     kpos, hi.x, lo.x)
            MKW(w_dcn, k0 + 8, n0,     kpos, hi.y, lo.y)
            MKW(w_dcn, k0,     n0 + 8, kpos, hi.z, lo.z)
            MKW(w_dcn, k0 + 8, n0 + 8, kpos, hi.w, lo.w)
            g_wfragH[idx] = hi;
            g_wfragL[idx] = lo;
        }
        for (int idx = t; idx < K2*384; idx += stride) {
            int kpos = idx / 384;
            int rem = idx - kpos*384;
            int tl = rem >> 5;        // kt*3 + ng
            int lane = rem & 31;
            int kt = tl / 3, ng = tl - kt*3;
            int n0 = ng*8 + (lane >> 2);
            int k0 = kt*16 + (lane & 3)*2;
            uint2 hi, lo;
            if (n0 < 18) {
                MKW(w_off, k0,     n0, kpos, hi.x, lo.x)
                MKW(w_off, k0 + 8, n0, kpos, hi.y, lo.y)
            } else {
                hi.x = hi.y = lo.x = lo.y = 0u;
            }
            g_wofH[idx] = hi;
            g_wofL[idx] = lo;
        }
#undef MKW
    }
}

// ============ kernel 2: offset conv via mma.sync (C=64 -> 18, 3x3, pad1) ============
#define OSA_HI 0
#define OSA_LO 16384
#define SMEM_OFF 32768

__global__ void __launch_bounds__(256)
k_offconv(const float* __restrict__ b_off) {
    char* sm = smraw;
    uint32_t sb = smem_u32(sm);
    int t = threadIdx.x;
    int lane = t & 31, warp = t >> 5;
    int blk = blockIdx.x;               // b*128 + h
    int b = blk >> 7, h = blk & 127;
    int pix0 = blk * WW;

    float acc[3][4];
#pragma unroll
    for (int i = 0; i < 3; i++)
#pragma unroll
        for (int j = 0; j < 4; j++) acc[i][j] = 0.f;

    int ltile = lane >> 3, lrow = lane & 7;
    int a_r = (ltile & 1)*8 + lrow;
    int a_gr = warp*16 + a_r;
    int a_cpar = ltile >> 1;
    uint32_t a_base = sb + a_gr*128;

    for (int k = 0; k < K2; k++) {
        int ky = k / 3, kx = k - ky*3;
        int y = h + ky - 1;
        bool vy = (unsigned)y < HH;
        const unsigned* hp = &g_xbf_hi[((size_t)(b*HH + (vy ? y : 0)))*WW*32];
        const unsigned* lp = &g_xbf_lo[((size_t)(b*HH + (vy ? y : 0)))*WW*32];
#pragma unroll 8
        for (int j = 0; j < 16; j++) {
            int p = warp*16 + j;
            int xx = p + kx - 1;
            bool v = vy && ((unsigned)xx < WW);
            unsigned h2 = v ? hp[xx*32 + lane] : 0u;
            unsigned l2 = v ? lp[xx*32 + lane] : 0u;
            unsigned off = p*128 + ((((lane >> 2) ^ (j & 7)) << 4) | ((lane & 3) << 2));
            *(unsigned*)(sm + OSA_HI + off) = h2;
            *(unsigned*)(sm + OSA_LO + off) = l2;
        }
        __syncwarp();

        const uint2* bfH = &g_wofH[k*384 + lane];
        const uint2* bfL = &g_wofL[k*384 + lane];
#pragma unroll
        for (int kt = 0; kt < 4; kt++) {
            uint32_t aH[4], aL[4];
            int chunkk = 2*kt + a_cpar;
            uint32_t addr = a_base + ((chunkk ^ (a_gr & 7)) << 4);
            ldsm4(aH, addr + OSA_HI);
            ldsm4(aL, addr + OSA_LO);
#pragma unroll
            for (int ng = 0; ng < 3; ng++) {
                uint2 BH = bfH[(kt*3 + ng)*32];
                uint2 BL = bfL[(kt*3 + ng)*32];
                mma16816(acc[ng], aH, BH.x, BH.y);
                mma16816(acc[ng], aL, BH.x, BH.y);
                mma16816(acc[ng], aH, BL.x, BL.y);
            }
        }
        __syncwarp();
    }

    int r0 = lane >> 2;
    int cq = (lane & 3)*2;
    int p0 = pix0 + warp*16 + r0;
    int p1 = p0 + 8;
#pragma unroll
    for (int ng = 0; ng < 3; ng++) {
        int col = ng*8 + cq;
        if (col < 18) {
            float bi0 = b_off[col], bi1 = b_off[col+1];
            g_offs[(size_t)p0*18 + col]     = acc[ng][0] + bi0;
            g_offs[(size_t)p0*18 + col + 1] = acc[ng][1] + bi1;
            g_offs[(size_t)p1*18 + col]     = acc[ng][2] + bi0;
            g_offs[(size_t)p1*18 + col + 1] = acc[ng][3] + bi1;
        }
    }
}

// ============ kernel 3: bilinear precompute (coalesced streaming) ============
__global__ void k_precomp() {
    int idx = blockIdx.x*blockDim.x + threadIdx.x;
    if (idx >= PIX*K2) return;
    int pix = idx / K2, k = idx - pix*K2;
    int hw = pix & (HW-1);
    int h = hw >> 7, w = hw & 127;
    float dy = g_offs[pix*18 + 2*k];
    float dx = g_offs[pix*18 + 2*k + 1];
    int ky = k / 3, kx = k - ky*3;
    float py = (float)(h + ky - 1) + dy;
    float px = (float)(w + kx - 1) + dx;
    float y0f = floorf(py), x0f = floorf(px);
    float wy = py - y0f, wx = px - x0f;
    int y0 = (int)y0f, x0 = (int)x0f;
    bool vy0 = (y0 >= 0) && (y0 < HH);
    bool vy1 = (y0 >= -1) && (y0 < HH-1);
    bool vx0 = (x0 >= 0) && (x0 < WW);
    bool vx1 = (x0 >= -1) && (x0 < WW-1);
    int iy0 = min(max(y0, 0), HH-1), iy1 = min(max(y0+1, 0), HH-1);
    int ix0 = min(max(x0, 0), WW-1), ix1 = min(max(x0+1, 0), WW-1);
    float4 wv;
    wv.x = (vy0 && vx0) ? (1.f-wy)*(1.f-wx) : 0.f;
    wv.y = (vy0 && vx1) ? (1.f-wy)*wx       : 0.f;
    wv.z = (vy1 && vx0) ? wy*(1.f-wx)       : 0.f;
    wv.w = (vy1 && vx1) ? wy*wx             : 0.f;
    int4 ov;
    ov.x = (iy0*WW + ix0)*CH*4;
    ov.y = (iy0*WW + ix1)*CH*4;
    ov.z = (iy1*WW + ix0)*CH*4;
    ov.w = (iy1*WW + ix1)*CH*4;
    g_pw[idx] = wv;
    g_po[idx] = ov;
}

// ============ kernel 4: deformable conv v13 (single-wave residency) ============
// Block: 128 threads = 4 warps, 64 pixels, 64 oc. Identical body to v12;
// __launch_bounds__(128, 7): 7 CTAs/SM x 148 SM = 1036 slots >= 1024 CTAs ->
// the ENTIRE grid runs as one wave (no 1.15-wave tail), 28 warps/SM.
#define SMA_HI 0
#define SMA_LO 8192
#define SMEM_DEF 16384

__global__ void __launch_bounds__(128, 7)
k_deform(const float* __restrict__ b_dcn, float* __restrict__ out) {
    char* sm = smraw;
    uint32_t sb = smem_u32(sm);
    int t = threadIdx.x;
    int lane = t & 31, warp = t >> 5;   // warp in [0,4)
    int blk = blockIdx.x;               // 0..1023
    int pix0 = blk * 64;
    int b = pix0 >> 14;
    int h = (pix0 & (HW-1)) >> 7;
    const char* xc = (const char*)&g_xn[(size_t)b * (HW*CH)];
    int m = lane & 15;                  // channel-quad index / pw-po holder index
    int lc4 = m * 16;                   // byte offset: 4 channels
    int psel = lane >> 4;               // which pixel of the pair

    float acc[8][4];
#pragma unroll
    for (int i = 0; i < 8; i++)
#pragma unroll
        for (int j = 0; j < 4; j++) acc[i][j] = 0.f;

    int ltile = lane >> 3, lrow = lane & 7;
    int a_r = (ltile & 1)*8 + lrow;
    int a_gr = warp*16 + a_r;           // local A row (0..63)
    int a_cpar = ltile >> 1;
    uint32_t a_base = sb + a_gr*128;

    // lane m holds pixel (warp*16 + m)'s pw/po
    size_t pp = (size_t)(pix0 + warp*16 + m)*K2;
    float4 pw_r = g_pw[pp];
    int4   po_r = g_po[pp];

    for (int k = 0; k < K2; k++) {
        // ---- gather 16 warp-local pixels: 2 chunks of 8 px (4 pairs each) ----
#pragma unroll
        for (int ch_ = 0; ch_ < 2; ch_++) {
            float4 part[4];
            {   // pass 1: top corners
                float4 c00[4], c01[4];
#pragma unroll
                for (int i = 0; i < 4; i++) {
                    int j = ch_*8 + 2*i + psel;
                    int o0 = __shfl_sync(0xffffffffu, po_r.x, j);
                    int o1 = __shfl_sync(0xffffffffu, po_r.y, j);
                    c00[i] = *(const float4*)(xc + o0 + lc4);
                    c01[i] = *(const float4*)(xc + o1 + lc4);
                }
#pragma unroll
                for (int i = 0; i < 4; i++) {
                    int j = ch_*8 + 2*i + psel;
                    float w0_ = __shfl_sync(0xffffffffu, pw_r.x, j);
                    float w1_ = __shfl_sync(0xffffffffu, pw_r.y, j);
                    part[i].x = w0_*c00[i].x + w1_*c01[i].x;
                    part[i].y = w0_*c00[i].y + w1_*c01[i].y;
                    part[i].z = w0_*c00[i].z + w1_*c01[i].z;
                    part[i].w = w0_*c00[i].w + w1_*c01[i].w;
                }
            }
            {   // pass 2: bottom corners + convert + store
                float4 c10[4], c11[4];
#pragma unroll
                for (int i = 0; i < 4; i++) {
                    int j = ch_*8 + 2*i + psel;
                    int o2 = __shfl_sync(0xffffffffu, po_r.z, j);
                    int o3 = __shfl_sync(0xffffffffu, po_r.w, j);
                    c10[i] = *(const float4*)(xc + o2 + lc4);
                    c11[i] = *(const float4*)(xc + o3 + lc4);
                }
#pragma unroll
                for (int i = 0; i < 4; i++) {
                    int j = ch_*8 + 2*i + psel;
                    float w2_ = __shfl_sync(0xffffffffu, pw_r.z, j);
                    float w3_ = __shfl_sync(0xffffffffu, pw_r.w, j);
                    float4 r;
                    r.x = part[i].x + w2_*c10[i].x + w3_*c11[i].x;
                    r.y = part[i].y + w2_*c10[i].y + w3_*c11[i].y;
                    r.z = part[i].z + w2_*c10[i].z + w3_*c11[i].z;
                    r.w = part[i].w + w2_*c10[i].w + w3_*c11[i].w;
                    unsigned h2a = pk_bf16x2(r.x, r.y);
                    unsigned h2b = pk_bf16x2(r.z, r.w);
                    float hx = __uint_as_float(h2a << 16);
                    float hy = __uint_as_float(h2a & 0xFFFF0000u);
                    float hz = __uint_as_float(h2b << 16);
                    float hw_ = __uint_as_float(h2b & 0xFFFF0000u);
                    unsigned l2a = pk_bf16x2(r.x - hx, r.y - hy);
                    unsigned l2b = pk_bf16x2(r.z - hz, r.w - hw_);
                    int p = warp*16 + ch_*8 + 2*i + psel;
                    unsigned off = p*128 + ((((m >> 1) ^ (p & 7)) << 4) | (((2*m) & 3) << 2));
                    *(uint2*)(sm + SMA_HI + off) = make_uint2(h2a, h2b);
                    *(uint2*)(sm + SMA_LO + off) = make_uint2(l2a, l2b);
                }
            }
        }
        __syncwarp();

        if (k < K2-1) {
            pw_r = g_pw[pp + k + 1];
            po_r = g_po[pp + k + 1];
        }

        // ---- GEMM: m16 x n64 x k64, 3-term bf16 split ----
        const uint4* bfH = &g_wfragH[k*512 + lane];
        const uint4* bfL = &g_wfragL[k*512 + lane];
#pragma unroll
        for (int kt = 0; kt < 4; kt++) {
            uint32_t aH[4], aL[4];
            int chunkk = 2*kt + a_cpar;
            uint32_t addr = a_base + ((chunkk ^ (a_gr & 7)) << 4);
            ldsm4(aH, addr + SMA_HI);
            ldsm4(aL, addr + SMA_LO);
#pragma unroll
            for (int ng = 0; ng < 4; ng++) {
                uint4 BH = bfH[(kt*4 + ng)*32];
                uint4 BL = bfL[(kt*4 + ng)*32];
                mma16816(acc[2*ng],   aH, BH.x, BH.y);
                mma16816(acc[2*ng],   aL, BH.x, BH.y);
                mma16816(acc[2*ng],   aH, BL.x, BL.y);
                mma16816(acc[2*ng+1], aH, BH.z, BH.w);
                mma16816(acc[2*ng+1], aL, BH.z, BH.w);
                mma16816(acc[2*ng+1], aH, BL.z, BL.w);
            }
        }
        __syncwarp();
    }

    // epilogue: write fragments to NCHW out
    int r0 = lane >> 2;
    int cq = (lane & 3)*2;
    int w0 = (pix0 & 127) + warp*16 + r0;
    size_t obase = (size_t)b*OC*HW + (size_t)h*WW;
#pragma unroll
    for (int nt = 0; nt < 8; nt++) {
        int oc = nt*8 + cq;
        float bias0 = b_dcn[oc];
        float bias1 = b_dcn[oc+1];
        float* o0 = &out[obase + (size_t)oc*HW];
        float* o1 = &out[obase + (size_t)(oc+1)*HW];
        o0[w0]     = acc[nt][0] + bias0;
        o1[w0]     = acc[nt][1] + bias1;
        o0[w0 + 8] = acc[nt][2] + bias0;
        o1[w0 + 8] = acc[nt][3] + bias1;
    }
}

// ============ launch ============
extern "C" void kernel_launch(void* const* d_in, const int* in_sizes, int n_in,
                              void* d_out, int out_size) {
    const float* x     = (const float*)d_in[0];
    const float* w_off = (const float*)d_in[1];
    const float* b_off = (const float*)d_in[2];
    const float* w_dcn = (const float*)d_in[3];
    const float* b_dcn = (const float*)d_in[4];
    float* out = (float*)d_out;

    cudaFuncSetAttribute(k_offconv, cudaFuncAttributeMaxDynamicSharedMemorySize, SMEM_OFF);
    cudaFuncSetAttribute(k_deform,  cudaFuncAttributeMaxDynamicSharedMemorySize, SMEM_DEF);

    k_transpose<<<dim3(WW/32, CH/32, BATCH*HH), dim3(32,8)>>>(x, w_off, w_dcn);
    k_offconv<<<BATCH*HH, 256, SMEM_OFF>>>(b_off);
    k_precomp<<<(PIX*K2 + 255)/256, 256>>>();
    k_deform<<<PIX/64, 128, SMEM_DEF>>>(b_dcn, out);
}

// round 15
// speedup vs baseline: 1.3845x; 1.1004x over previous
#include <cuda_runtime.h>
#include <cuda_bf16.h>
#include <math.h>
#include <stdint.h>

#define BATCH 4
#define CH 64
#define OC 64
#define HH 128
#define WW 128
#define HW (HH*WW)
#define PIX (BATCH*HW)
#define K2 9
#define KKD 576            // K2*CH

// -------- device scratch (no allocations allowed) --------
__device__ float g_xn[PIX*CH];            // x in NHWC fp32: [b][h][w][c]
__device__ unsigned g_xbf_hi[PIX*32];     // x bf16 hi plane: [pix][cpair]
__device__ unsigned g_xbf_lo[PIX*32];     // x bf16 lo plane
__device__ float g_offs[PIX*18];          // offsets: [pix][18]
__device__ uint4 g_wfragH[K2*512];        // deform B hi frags: [k][kt*4+ng][lane]
__device__ uint4 g_wfragL[K2*512];        // deform B lo frags
__device__ uint2 g_wofH[K2*384];          // offconv B hi frags: [k][kt*3+ng][lane]
__device__ uint2 g_wofL[K2*384];          // offconv B lo frags
__device__ float4 g_pw[PIX*K2];           // bilinear weights (validity folded)
__device__ int4  g_po[PIX*K2];            // per-corner clamped byte offsets

// single dynamic-shared symbol shared by all kernels
extern __shared__ char smraw[];

// pack two fp32 -> bf16x2 (first arg -> lower 16 bits)
__device__ __forceinline__ unsigned pk_bf16x2(float lo, float hi) {
    unsigned r;
    asm("cvt.rn.bf16x2.f32 %0, %1, %2;" : "=r"(r) : "f"(hi), "f"(lo));
    return r;
}
__device__ __forceinline__ uint32_t smem_u32(const void* p) {
    uint32_t a;
    asm("{ .reg .u64 t; cvta.to.shared.u64 t, %1; cvt.u32.u64 %0, t; }" : "=r"(a) : "l"(p));
    return a;
}
__device__ __forceinline__ void ldsm4(uint32_t* r, uint32_t addr) {
    asm volatile("ldmatrix.sync.aligned.m8n8.x4.shared.b16 {%0,%1,%2,%3}, [%4];"
        : "=r"(r[0]), "=r"(r[1]), "=r"(r[2]), "=r"(r[3]) : "r"(addr));
}
__device__ __forceinline__ void mma16816(float* c, const uint32_t* a, uint32_t b0, uint32_t b1) {
    asm volatile("mma.sync.aligned.m16n8k16.row.col.f32.bf16.bf16.f32 "
        "{%0,%1,%2,%3}, {%4,%5,%6,%7}, {%8,%9}, {%0,%1,%2,%3};"
        : "+f"(c[0]), "+f"(c[1]), "+f"(c[2]), "+f"(c[3])
        : "r"(a[0]), "r"(a[1]), "r"(a[2]), "r"(a[3]), "r"(b0), "r"(b1));
}

// ============ kernel 1: transpose + bf16 planes + (folded) weight reorder ============
__global__ void k_transpose(const float* __restrict__ x,
                            const float* __restrict__ w_off,
                            const float* __restrict__ w_dcn) {
    __shared__ float tile[32][33];
    int bh = blockIdx.z;                 // b*128 + h
    int c0 = blockIdx.y * 32;
    int w0 = blockIdx.x * 32;
    int b = bh >> 7, h = bh & 127;
    int tx = threadIdx.x, ty = threadIdx.y;
#pragma unroll
    for (int i = 0; i < 4; i++) {
        int c = c0 + ty + i*8;
        tile[ty + i*8][tx] = x[((b*CH + c)*HH + h)*WW + w0 + tx];
    }
    __syncthreads();
#pragma unroll
    for (int i = 0; i < 4; i++) {
        int w = w0 + ty + i*8;
        g_xn[(bh*WW + w)*CH + c0 + tx] = tile[tx][ty + i*8];
    }
    if (tx < 16) {
#pragma unroll
        for (int i = 0; i < 4; i++) {
            int wi = ty + i*8;
            int w = w0 + wi;
            float v0 = tile[2*tx][wi];
            float v1 = tile[2*tx + 1][wi];
            unsigned h2 = pk_bf16x2(v0, v1);
            float h0 = __uint_as_float(h2 << 16);
            float h1 = __uint_as_float(h2 & 0xFFFF0000u);
            unsigned l2 = pk_bf16x2(v0 - h0, v1 - h1);
            int idx = (bh*WW + w)*32 + (c0 >> 1) + tx;
            g_xbf_hi[idx] = h2;
            g_xbf_lo[idx] = l2;
        }
    }

    // ---- folded weight reorder (sub-grid slice: x==0 && y==0 -> 512 blocks) ----
    if (blockIdx.x == 0 && blockIdx.y == 0) {
        int t = blockIdx.z*256 + ty*32 + tx;
        int stride = 512*256;
        unsigned hw_, lw_;
        float a0, a1, h0, h1;
#define MKW(SRC, KK, NN, KP, HRES, LRES) \
        a0 = SRC[(NN)*KKD + (KK)*K2 + KP]; \
        a1 = SRC[(NN)*KKD + (KK+1)*K2 + KP]; \
        hw_ = pk_bf16x2(a0, a1); \
        h0 = __uint_as_float(hw_ << 16); \
        h1 = __uint_as_float(hw_ & 0xFFFF0000u); \
        lw_ = pk_bf16x2(a0 - h0, a1 - h1); \
        HRES = hw_; LRES = lw_;
        for (int idx = t; idx < K2*512; idx += stride) {
            int kpos = idx / 512;
            int rem = idx & 511;
            int tl = rem >> 5;        // kt*4 + ng
            int lane = rem & 31;
            int kt = tl >> 2, ng = tl & 3;
            int n0 = ng*16 + (lane >> 2);
            int k0 = kt*16 + (lane & 3)*2;
            uint4 hi, lo;
            MKW(w_dcn, k0,     n0,     kpos, hi.x, lo.x)
            MKW(w_dcn, k0 + 8, n0,     kpos, hi.y, lo.y)
            MKW(w_dcn, k0,     n0 + 8, kpos, hi.z, lo.z)
            MKW(w_dcn, k0 + 8, n0 + 8, kpos, hi.w, lo.w)
            g_wfragH[idx] = hi;
            g_wfragL[idx] = lo;
        }
        for (int idx = t; idx < K2*384; idx += stride) {
            int kpos = idx / 384;
            int rem = idx - kpos*384;
            int tl = rem >> 5;        // kt*3 + ng
            int lane = rem & 31;
            int kt = tl / 3, ng = tl - kt*3;
            int n0 = ng*8 + (lane >> 2);
            int k0 = kt*16 + (lane & 3)*2;
            uint2 hi, lo;
            if (n0 < 18) {
                MKW(w_off, k0,     n0, kpos, hi.x, lo.x)
                MKW(w_off, k0 + 8, n0, kpos, hi.y, lo.y)
            } else {
                hi.x = hi.y = lo.x = lo.y = 0u;
            }
            g_wofH[idx] = hi;
            g_wofL[idx] = lo;
        }
#undef MKW
    }
}

// ============ kernel 2: offset conv via mma.sync (C=64 -> 18, 3x3, pad1) ============
#define OSA_HI 0
#define OSA_LO 16384
#define SMEM_OFF 32768

__global__ void __launch_bounds__(256)
k_offconv(const float* __restrict__ b_off) {
    char* sm = smraw;
    uint32_t sb = smem_u32(sm);
    int t = threadIdx.x;
    int lane = t & 31, warp = t >> 5;
    int blk = blockIdx.x;               // b*128 + h
    int b = blk >> 7, h = blk & 127;
    int pix0 = blk * WW;

    float acc[3][4];
#pragma unroll
    for (int i = 0; i < 3; i++)
#pragma unroll
        for (int j = 0; j < 4; j++) acc[i][j] = 0.f;

    int ltile = lane >> 3, lrow = lane & 7;
    int a_r = (ltile & 1)*8 + lrow;
    int a_gr = warp*16 + a_r;
    int a_cpar = ltile >> 1;
    uint32_t a_base = sb + a_gr*128;

    for (int k = 0; k < K2; k++) {
        int ky = k / 3, kx = k - ky*3;
        int y = h + ky - 1;
        bool vy = (unsigned)y < HH;
        const unsigned* hp = &g_xbf_hi[((size_t)(b*HH + (vy ? y : 0)))*WW*32];
        const unsigned* lp = &g_xbf_lo[((size_t)(b*HH + (vy ? y : 0)))*WW*32];
#pragma unroll 8
        for (int j = 0; j < 16; j++) {
            int p = warp*16 + j;
            int xx = p + kx - 1;
            bool v = vy && ((unsigned)xx < WW);
            unsigned h2 = v ? hp[xx*32 + lane] : 0u;
            unsigned l2 = v ? lp[xx*32 + lane] : 0u;
            unsigned off = p*128 + ((((lane >> 2) ^ (j & 7)) << 4) | ((lane & 3) << 2));
            *(unsigned*)(sm + OSA_HI + off) = h2;
            *(unsigned*)(sm + OSA_LO + off) = l2;
        }
        __syncwarp();

        const uint2* bfH = &g_wofH[k*384 + lane];
        const uint2* bfL = &g_wofL[k*384 + lane];
#pragma unroll
        for (int kt = 0; kt < 4; kt++) {
            uint32_t aH[4], aL[4];
            int chunkk = 2*kt + a_cpar;
            uint32_t addr = a_base + ((chunkk ^ (a_gr & 7)) << 4);
            ldsm4(aH, addr + OSA_HI);
            ldsm4(aL, addr + OSA_LO);
#pragma unroll
            for (int ng = 0; ng < 3; ng++) {
                uint2 BH = bfH[(kt*3 + ng)*32];
                uint2 BL = bfL[(kt*3 + ng)*32];
                mma16816(acc[ng], aH, BH.x, BH.y);
                mma16816(acc[ng], aL, BH.x, BH.y);
                mma16816(acc[ng], aH, BL.x, BL.y);
            }
        }
        __syncwarp();
    }

    int r0 = lane >> 2;
    int cq = (lane & 3)*2;
    int p0 = pix0 + warp*16 + r0;
    int p1 = p0 + 8;
#pragma unroll
    for (int ng = 0; ng < 3; ng++) {
        int col = ng*8 + cq;
        if (col < 18) {
            float bi0 = b_off[col], bi1 = b_off[col+1];
            g_offs[(size_t)p0*18 + col]     = acc[ng][0] + bi0;
            g_offs[(size_t)p0*18 + col + 1] = acc[ng][1] + bi1;
            g_offs[(size_t)p1*18 + col]     = acc[ng][2] + bi0;
            g_offs[(size_t)p1*18 + col + 1] = acc[ng][3] + bi1;
        }
    }
}

// ============ kernel 3: bilinear precompute (coalesced streaming) ============
__global__ void k_precomp() {
    int idx = blockIdx.x*blockDim.x + threadIdx.x;
    if (idx >= PIX*K2) return;
    int pix = idx / K2, k = idx - pix*K2;
    int hw = pix & (HW-1);
    int h = hw >> 7, w = hw & 127;
    float dy = g_offs[pix*18 + 2*k];
    float dx = g_offs[pix*18 + 2*k + 1];
    int ky = k / 3, kx = k - ky*3;
    float py = (float)(h + ky - 1) + dy;
    float px = (float)(w + kx - 1) + dx;
    float y0f = floorf(py), x0f = floorf(px);
    float wy = py - y0f, wx = px - x0f;
    int y0 = (int)y0f, x0 = (int)x0f;
    bool vy0 = (y0 >= 0) && (y0 < HH);
    bool vy1 = (y0 >= -1) && (y0 < HH-1);
    bool vx0 = (x0 >= 0) && (x0 < WW);
    bool vx1 = (x0 >= -1) && (x0 < WW-1);
    int iy0 = min(max(y0, 0), HH-1), iy1 = min(max(y0+1, 0), HH-1);
    int ix0 = min(max(x0, 0), WW-1), ix1 = min(max(x0+1, 0), WW-1);
    float4 wv;
    wv.x = (vy0 && vx0) ? (1.f-wy)*(1.f-wx) : 0.f;
    wv.y = (vy0 && vx1) ? (1.f-wy)*wx       : 0.f;
    wv.z = (vy1 && vx0) ? wy*(1.f-wx)       : 0.f;
    wv.w = (vy1 && vx1) ? wy*wx             : 0.f;
    int4 ov;
    ov.x = (iy0*WW + ix0)*CH*4;
    ov.y = (iy0*WW + ix1)*CH*4;
    ov.z = (iy1*WW + ix0)*CH*4;
    ov.w = (iy1*WW + ix1)*CH*4;
    g_pw[idx] = wv;
    g_po[idx] = ov;
}

// ============ kernel 4: deformable conv v14 (m32/warp, single wave) ============
// Block: 128 threads = 4 warps, 128 pixels (one image row), 64 oc. Warp tile
// m32 x n64: B fragments amortize over 2x pixels (-30% L1 wf/px — the round-14
// profile shows L1=80% as the binder). grid=512 @ __launch_bounds__(128,4):
// 592 slots >= 512 -> single wave (the reason round-12's m32 failed: 444<512).
// Gather: 8 chunks of 2 pixel-pairs (paired float4 loads), 2-pass corners,
// peak regs ~105 < 128 cap.
#define SMA_HI 0
#define SMA_LO 16384
#define SMEM_DEF 32768

__global__ void __launch_bounds__(128, 4)
k_deform(const float* __restrict__ b_dcn, float* __restrict__ out) {
    char* sm = smraw;
    uint32_t sb = smem_u32(sm);
    int t = threadIdx.x;
    int lane = t & 31, warp = t >> 5;   // warp in [0,4)
    int blk = blockIdx.x;               // b*128 + h
    int pix0 = blk * 128;
    int b = pix0 >> 14;
    int h = (pix0 & (HW-1)) >> 7;
    const char* xc = (const char*)&g_xn[(size_t)b * (HW*CH)];
    int m = lane & 15;                  // channel-quad index
    int lc4 = m * 16;                   // byte offset: 4 channels
    int psel = lane >> 4;               // which pixel of the pair

    float acc[2][8][4];
#pragma unroll
    for (int mt = 0; mt < 2; mt++)
#pragma unroll
        for (int i = 0; i < 8; i++)
#pragma unroll
            for (int j = 0; j < 4; j++) acc[mt][i][j] = 0.f;

    int ltile = lane >> 3, lrow = lane & 7;
    int a_r = (ltile & 1)*8 + lrow;
    int a_cpar = ltile >> 1;
    int a_gr0 = warp*32 + a_r;          // local A rows for the two m16 tiles
    int a_gr1 = a_gr0 + 16;

    // lane j holds pixel (warp*32 + j)'s pw/po
    size_t pp = (size_t)(pix0 + warp*32 + lane)*K2;
    float4 pw_r = g_pw[pp];
    int4   po_r = g_po[pp];

    for (int k = 0; k < K2; k++) {
        // ---- gather 32 warp-local pixels: 8 chunks of 4 px (2 pairs) ----
#pragma unroll
        for (int ch_ = 0; ch_ < 8; ch_++) {
            float4 part[2];
            {   // pass 1: top corners
                float4 c00[2], c01[2];
#pragma unroll
                for (int i = 0; i < 2; i++) {
                    int j = ch_*4 + 2*i + psel;
                    int o0 = __shfl_sync(0xffffffffu, po_r.x, j);
                    int o1 = __shfl_sync(0xffffffffu, po_r.y, j);
                    c00[i] = *(const float4*)(xc + o0 + lc4);
                    c01[i] = *(const float4*)(xc + o1 + lc4);
                }
#pragma unroll
                for (int i = 0; i < 2; i++) {
                    int j = ch_*4 + 2*i + psel;
                    float w0_ = __shfl_sync(0xffffffffu, pw_r.x, j);
                    float w1_ = __shfl_sync(0xffffffffu, pw_r.y, j);
                    part[i].x = w0_*c00[i].x + w1_*c01[i].x;
                    part[i].y = w0_*c00[i].y + w1_*c01[i].y;
                    part[i].z = w0_*c00[i].z + w1_*c01[i].z;
                    part[i].w = w0_*c00[i].w + w1_*c01[i].w;
                }
            }
            {   // pass 2: bottom corners + convert + store
                float4 c10[2], c11[2];
#pragma unroll
                for (int i = 0; i < 2; i++) {
                    int j = ch_*4 + 2*i + psel;
                    int o2 = __shfl_sync(0xffffffffu, po_r.z, j);
                    int o3 = __shfl_sync(0xffffffffu, po_r.w, j);
                    c10[i] = *(const float4*)(xc + o2 + lc4);
                    c11[i] = *(const float4*)(xc + o3 + lc4);
                }
#pragma unroll
                for (int i = 0; i < 2; i++) {
                    int j = ch_*4 + 2*i + psel;
                    float w2_ = __shfl_sync(0xffffffffu, pw_r.z, j);
                    float w3_ = __shfl_sync(0xffffffffu, pw_r.w, j);
                    float4 r;
                    r.x = part[i].x + w2_*c10[i].x + w3_*c11[i].x;
                    r.y = part[i].y + w2_*c10[i].y + w3_*c11[i].y;
                    r.z = part[i].z + w2_*c10[i].z + w3_*c11[i].z;
                    r.w = part[i].w + w2_*c10[i].w + w3_*c11[i].w;
                    unsigned h2a = pk_bf16x2(r.x, r.y);
                    unsigned h2b = pk_bf16x2(r.z, r.w);
                    float hx = __uint_as_float(h2a << 16);
                    float hy = __uint_as_float(h2a & 0xFFFF0000u);
                    float hz = __uint_as_float(h2b << 16);
                    float hw_ = __uint_as_float(h2b & 0xFFFF0000u);
                    unsigned l2a = pk_bf16x2(r.x - hx, r.y - hy);
                    unsigned l2b = pk_bf16x2(r.z - hz, r.w - hw_);
                    int p = warp*32 + ch_*4 + 2*i + psel;
                    unsigned off = p*128 + ((((m >> 1) ^ (p & 7)) << 4) | (((2*m) & 3) << 2));
                    *(uint2*)(sm + SMA_HI + off) = make_uint2(h2a, h2b);
                    *(uint2*)(sm + SMA_LO + off) = make_uint2(l2a, l2b);
                }
            }
        }
        __syncwarp();

        if (k < K2-1) {
            pw_r = g_pw[pp + k + 1];
            po_r = g_po[pp + k + 1];
        }

        // ---- GEMM: m32 x n64 x k64, 3-term bf16 split; B loaded once per kt ----
        const uint4* bfH = &g_wfragH[k*512 + lane];
        const uint4* bfL = &g_wfragL[k*512 + lane];
#pragma unroll
        for (int kt = 0; kt < 4; kt++) {
            uint32_t aH0[4], aL0[4], aH1[4], aL1[4];
            int chunkk = 2*kt + a_cpar;
            uint32_t ad0 = sb + a_gr0*128 + ((chunkk ^ lrow) << 4);
            uint32_t ad1 = sb + a_gr1*128 + ((chunkk ^ lrow) << 4);
            ldsm4(aH0, ad0 + SMA_HI);
            ldsm4(aL0, ad0 + SMA_LO);
            ldsm4(aH1, ad1 + SMA_HI);
            ldsm4(aL1, ad1 + SMA_LO);
#pragma unroll
            for (int ng = 0; ng < 4; ng++) {
                uint4 BH = bfH[(kt*4 + ng)*32];
                uint4 BL = bfL[(kt*4 + ng)*32];
                mma16816(acc[0][2*ng],   aH0, BH.x, BH.y);
                mma16816(acc[0][2*ng],   aL0, BH.x, BH.y);
                mma16816(acc[0][2*ng],   aH0, BL.x, BL.y);
                mma16816(acc[0][2*ng+1], aH0, BH.z, BH.w);
                mma16816(acc[0][2*ng+1], aL0, BH.z, BH.w);
                mma16816(acc[0][2*ng+1], aH0, BL.z, BL.w);
                mma16816(acc[1][2*ng],   aH1, BH.x, BH.y);
                mma16816(acc[1][2*ng],   aL1, BH.x, BH.y);
                mma16816(acc[1][2*ng],   aH1, BL.x, BL.y);
                mma16816(acc[1][2*ng+1], aH1, BH.z, BH.w);
                mma16816(acc[1][2*ng+1], aL1, BH.z, BH.w);
                mma16816(acc[1][2*ng+1], aH1, BL.z, BL.w);
            }
        }
        __syncwarp();
    }

    // epilogue: write fragments to NCHW out (two m16 tiles)
    int r0 = lane >> 2;
    int cq = (lane & 3)*2;
    size_t obase = (size_t)b*OC*HW + (size_t)h*WW;
#pragma unroll
    for (int mt = 0; mt < 2; mt++) {
        int w0 = warp*32 + mt*16 + r0;
#pragma unroll
        for (int nt = 0; nt < 8; nt++) {
            int oc = nt*8 + cq;
            float bias0 = b_dcn[oc];
            float bias1 = b_dcn[oc+1];
            float* o0 = &out[obase + (size_t)oc*HW];
            float* o1 = &out[obase + (size_t)(oc+1)*HW];
            o0[w0]     = acc[mt][nt][0] + bias0;
            o1[w0]     = acc[mt][nt][1] + bias1;
            o0[w0 + 8] = acc[mt][nt][2] + bias0;
            o1[w0 + 8] = acc[mt][nt][3] + bias1;
        }
    }
}

// ============ launch ============
extern "C" void kernel_launch(void* const* d_in, const int* in_sizes, int n_in,
                              void* d_out, int out_size) {
    const float* x     = (const float*)d_in[0];
    const float* w_off = (const float*)d_in[1];
    const float* b_off = (const float*)d_in[2];
    const float* w_dcn = (const float*)d_in[3];
    const float* b_dcn = (const float*)d_in[4];
    float* out = (float*)d_out;

    cudaFuncSetAttribute(k_offconv, cudaFuncAttributeMaxDynamicSharedMemorySize, SMEM_OFF);
    cudaFuncSetAttribute(k_deform,  cudaFuncAttributeMaxDynamicSharedMemorySize, SMEM_DEF);

    k_transpose<<<dim3(WW/32, CH/32, BATCH*HH), dim3(32,8)>>>(x, w_off, w_dcn);
    k_offconv<<<BATCH*HH, 256, SMEM_OFF>>>(b_off);
    k_precomp<<<(PIX*K2 + 255)/256, 256>>>();
    k_deform<<<PIX/128, 128, SMEM_DEF>>>(b_dcn, out);
}

// round 16
// speedup vs baseline: 1.5230x; 1.1000x over previous
#include <cuda_runtime.h>
#include <cuda_bf16.h>
#include <math.h>
#include <stdint.h>

#define BATCH 4
#define CH 64
#define OC 64
#define HH 128
#define WW 128
#define HW (HH*WW)
#define PIX (BATCH*HW)
#define K2 9
#define KKD 576            // K2*CH

// -------- device scratch (no allocations allowed) --------
__device__ float g_xn[PIX*CH];            // x in NHWC fp32: [b][h][w][c]
__device__ unsigned g_xbf_hi[PIX*32];     // x bf16 hi plane: [pix][cpair]
__device__ unsigned g_xbf_lo[PIX*32];     // x bf16 lo plane
__device__ float g_offsT[K2*PIX*2];       // offsets k-major: [k][pix] = (dy,dx)
__device__ uint4 g_wfragH[K2*512];        // deform B hi frags: [k][kt*4+ng][lane]
__device__ uint4 g_wfragL[K2*512];        // deform B lo frags
__device__ uint2 g_wofH[K2*384];          // offconv B hi frags: [k][kt*3+ng][lane]
__device__ uint2 g_wofL[K2*384];          // offconv B lo frags

// single dynamic-shared symbol shared by all kernels
extern __shared__ char smraw[];

// pack two fp32 -> bf16x2 (first arg -> lower 16 bits)
__device__ __forceinline__ unsigned pk_bf16x2(float lo, float hi) {
    unsigned r;
    asm("cvt.rn.bf16x2.f32 %0, %1, %2;" : "=r"(r) : "f"(hi), "f"(lo));
    return r;
}
__device__ __forceinline__ uint32_t smem_u32(const void* p) {
    uint32_t a;
    asm("{ .reg .u64 t; cvta.to.shared.u64 t, %1; cvt.u32.u64 %0, t; }" : "=r"(a) : "l"(p));
    return a;
}
__device__ __forceinline__ void ldsm4(uint32_t* r, uint32_t addr) {
    asm volatile("ldmatrix.sync.aligned.m8n8.x4.shared.b16 {%0,%1,%2,%3}, [%4];"
        : "=r"(r[0]), "=r"(r[1]), "=r"(r[2]), "=r"(r[3]) : "r"(addr));
}
__device__ __forceinline__ void mma16816(float* c, const uint32_t* a, uint32_t b0, uint32_t b1) {
    asm volatile("mma.sync.aligned.m16n8k16.row.col.f32.bf16.bf16.f32 "
        "{%0,%1,%2,%3}, {%4,%5,%6,%7}, {%8,%9}, {%0,%1,%2,%3};"
        : "+f"(c[0]), "+f"(c[1]), "+f"(c[2]), "+f"(c[3])
        : "r"(a[0]), "r"(a[1]), "r"(a[2]), "r"(a[3]), "r"(b0), "r"(b1));
}

// ============ kernel 1: transpose + bf16 planes + (folded) weight reorder ============
__global__ void k_transpose(const float* __restrict__ x,
                            const float* __restrict__ w_off,
                            const float* __restrict__ w_dcn) {
    __shared__ float tile[32][33];
    int bh = blockIdx.z;                 // b*128 + h
    int c0 = blockIdx.y * 32;
    int w0 = blockIdx.x * 32;
    int b = bh >> 7, h = bh & 127;
    int tx = threadIdx.x, ty = threadIdx.y;
#pragma unroll
    for (int i = 0; i < 4; i++) {
        int c = c0 + ty + i*8;
        tile[ty + i*8][tx] = x[((b*CH + c)*HH + h)*WW + w0 + tx];
    }
    __syncthreads();
#pragma unroll
    for (int i = 0; i < 4; i++) {
        int w = w0 + ty + i*8;
        g_xn[(bh*WW + w)*CH + c0 + tx] = tile[tx][ty + i*8];
    }
    if (tx < 16) {
#pragma unroll
        for (int i = 0; i < 4; i++) {
            int wi = ty + i*8;
            int w = w0 + wi;
            float v0 = tile[2*tx][wi];
            float v1 = tile[2*tx + 1][wi];
            unsigned h2 = pk_bf16x2(v0, v1);
            float h0 = __uint_as_float(h2 << 16);
            float h1 = __uint_as_float(h2 & 0xFFFF0000u);
            unsigned l2 = pk_bf16x2(v0 - h0, v1 - h1);
            int idx = (bh*WW + w)*32 + (c0 >> 1) + tx;
            g_xbf_hi[idx] = h2;
            g_xbf_lo[idx] = l2;
        }
    }

    // ---- folded weight reorder (sub-grid slice: x==0 && y==0 -> 512 blocks) ----
    if (blockIdx.x == 0 && blockIdx.y == 0) {
        int t = blockIdx.z*256 + ty*32 + tx;
        int stride = 512*256;
        unsigned hw_, lw_;
        float a0, a1, h0, h1;
#define MKW(SRC, KK, NN, KP, HRES, LRES) \
        a0 = SRC[(NN)*KKD + (KK)*K2 + KP]; \
        a1 = SRC[(NN)*KKD + (KK+1)*K2 + KP]; \
        hw_ = pk_bf16x2(a0, a1); \
        h0 = __uint_as_float(hw_ << 16); \
        h1 = __uint_as_float(hw_ & 0xFFFF0000u); \
        lw_ = pk_bf16x2(a0 - h0, a1 - h1); \
        HRES = hw_; LRES = lw_;
        for (int idx = t; idx < K2*512; idx += stride) {
            int kpos = idx / 512;
            int rem = idx & 511;
            int tl = rem >> 5;        // kt*4 + ng
            int lane = rem & 31;
            int kt = tl >> 2, ng = tl & 3;
            int n0 = ng*16 + (lane >> 2);
            int k0 = kt*16 + (lane & 3)*2;
            uint4 hi, lo;
            MKW(w_dcn, k0,     n0,     kpos, hi.x, lo.x)
            MKW(w_dcn, k0 + 8, n0,     kpos, hi.y, lo.y)
            MKW(w_dcn, k0,     n0 + 8, kpos, hi.z, lo.z)
            MKW(w_dcn, k0 + 8, n0 + 8, kpos, hi.w, lo.w)
            g_wfragH[idx] = hi;
            g_wfragL[idx] = lo;
        }
        for (int idx = t; idx < K2*384; idx += stride) {
            int kpos = idx / 384;
            int rem = idx - kpos*384;
            int tl = rem >> 5;        // kt*3 + ng
            int lane = rem & 31;
            int kt = tl / 3, ng = tl - kt*3;
            int n0 = ng*8 + (lane >> 2);
            int k0 = kt*16 + (lane & 3)*2;
            uint2 hi, lo;
            if (n0 < 18) {
                MKW(w_off, k0,     n0, kpos, hi.x, lo.x)
                MKW(w_off, k0 + 8, n0, kpos, hi.y, lo.y)
            } else {
                hi.x = hi.y = lo.x = lo.y = 0u;
            }
            g_wofH[idx] = hi;
            g_wofL[idx] = lo;
        }
#undef MKW
    }
}

// ============ kernel 2: offset conv via mma.sync (C=64 -> 18, 3x3, pad1) ============
// Epilogue writes offsets k-major: g_offsT[k][pix] = (dy,dx).
#define OSA_HI 0
#define OSA_LO 16384
#define SMEM_OFF 32768

__global__ void __launch_bounds__(256)
k_offconv(const float* __restrict__ b_off) {
    char* sm = smraw;
    uint32_t sb = smem_u32(sm);
    int t = threadIdx.x;
    int lane = t & 31, warp = t >> 5;
    int blk = blockIdx.x;               // b*128 + h
    int b = blk >> 7, h = blk & 127;
    int pix0 = blk * WW;

    float acc[3][4];
#pragma unroll
    for (int i = 0; i < 3; i++)
#pragma unroll
        for (int j = 0; j < 4; j++) acc[i][j] = 0.f;

    int ltile = lane >> 3, lrow = lane & 7;
    int a_r = (ltile & 1)*8 + lrow;
    int a_gr = warp*16 + a_r;
    int a_cpar = ltile >> 1;
    uint32_t a_base = sb + a_gr*128;

    for (int k = 0; k < K2; k++) {
        int ky = k / 3, kx = k - ky*3;
        int y = h + ky - 1;
        bool vy = (unsigned)y < HH;
        const unsigned* hp = &g_xbf_hi[((size_t)(b*HH + (vy ? y : 0)))*WW*32];
        const unsigned* lp = &g_xbf_lo[((size_t)(b*HH + (vy ? y : 0)))*WW*32];
#pragma unroll 8
        for (int j = 0; j < 16; j++) {
            int p = warp*16 + j;
            int xx = p + kx - 1;
            bool v = vy && ((unsigned)xx < WW);
            unsigned h2 = v ? hp[xx*32 + lane] : 0u;
            unsigned l2 = v ? lp[xx*32 + lane] : 0u;
            unsigned off = p*128 + ((((lane >> 2) ^ (j & 7)) << 4) | ((lane & 3) << 2));
            *(unsigned*)(sm + OSA_HI + off) = h2;
            *(unsigned*)(sm + OSA_LO + off) = l2;
        }
        __syncwarp();

        const uint2* bfH = &g_wofH[k*384 + lane];
        const uint2* bfL = &g_wofL[k*384 + lane];
#pragma unroll
        for (int kt = 0; kt < 4; kt++) {
            uint32_t aH[4], aL[4];
            int chunkk = 2*kt + a_cpar;
            uint32_t addr = a_base + ((chunkk ^ (a_gr & 7)) << 4);
            ldsm4(aH, addr + OSA_HI);
            ldsm4(aL, addr + OSA_LO);
#pragma unroll
            for (int ng = 0; ng < 3; ng++) {
                uint2 BH = bfH[(kt*3 + ng)*32];
                uint2 BL = bfL[(kt*3 + ng)*32];
                mma16816(acc[ng], aH, BH.x, BH.y);
                mma16816(acc[ng], aL, BH.x, BH.y);
                mma16816(acc[ng], aH, BL.x, BL.y);
            }
        }
        __syncwarp();
    }

    // epilogue: each valid (ng, lane&3) holds (dy,dx) of position kk for 2 pixels
    int r0 = lane >> 2;
    int cq = (lane & 3)*2;
    int p0 = pix0 + warp*16 + r0;
    int p1 = p0 + 8;
    float2* offT = (float2*)g_offsT;
#pragma unroll
    for (int ng = 0; ng < 3; ng++) {
        int col = ng*8 + cq;
        if (col < 18) {
            int kk = col >> 1;
            float bi0 = b_off[col], bi1 = b_off[col+1];
            offT[(size_t)kk*PIX + p0] = make_float2(acc[ng][0] + bi0, acc[ng][1] + bi1);
            offT[(size_t)kk*PIX + p1] = make_float2(acc[ng][2] + bi0, acc[ng][3] + bi1);
        }
    }
}

// ============ kernel 3: deformable conv v15 (inline bilinear precompute) ============
// Block: 128 threads = 4 warps, 128 pixels (one image row), 64 oc. Warp tile
// m32 x n64 (B frags amortized over 2x pixels). grid=512 @ (128,4) -> single
// wave. Offsets read per position as ONE coalesced float2 (k-major layout);
// pw/po computed inline (~25 ALU) — k_precomp kernel and g_pw/g_po tables gone.
#define SMA_HI 0
#define SMA_LO 16384
#define SMEM_DEF 32768

__global__ void __launch_bounds__(128, 4)
k_deform(const float* __restrict__ b_dcn, float* __restrict__ out) {
    char* sm = smraw;
    uint32_t sb = smem_u32(sm);
    int t = threadIdx.x;
    int lane = t & 31, warp = t >> 5;   // warp in [0,4)
    int blk = blockIdx.x;               // b*128 + h
    int pix0 = blk * 128;
    int b = pix0 >> 14;
    int h = (pix0 & (HW-1)) >> 7;
    const char* xc = (const char*)&g_xn[(size_t)b * (HW*CH)];
    int m = lane & 15;                  // channel-quad index
    int lc4 = m * 16;                   // byte offset: 4 channels
    int psel = lane >> 4;               // which pixel of the pair

    float acc[2][8][4];
#pragma unroll
    for (int mt = 0; mt < 2; mt++)
#pragma unroll
        for (int i = 0; i < 8; i++)
#pragma unroll
            for (int j = 0; j < 4; j++) acc[mt][i][j] = 0.f;

    int ltile = lane >> 3, lrow = lane & 7;
    int a_r = (ltile & 1)*8 + lrow;
    int a_cpar = ltile >> 1;
    int a_gr0 = warp*32 + a_r;          // local A rows for the two m16 tiles
    int a_gr1 = a_gr0 + 16;

    // thread t <-> pixel pix0 + t (w = t); coalesced k-major offset loads
    const float2* offT = (const float2*)g_offsT;
    int gpix = pix0 + t;
    float2 od = offT[gpix];             // k = 0 plane

    for (int k = 0; k < K2; k++) {
        // ---- inline bilinear precompute from (dy,dx) ----
        float4 pw_r;
        int4   po_r;
        {
            int ky = k / 3, kx = k - ky*3;
            float py = (float)(h + ky - 1) + od.x;
            float px = (float)(t + kx - 1) + od.y;
            float y0f = floorf(py), x0f = floorf(px);
            float wy = py - y0f, wx = px - x0f;
            int y0 = (int)y0f, x0 = (int)x0f;
            bool vy0 = (y0 >= 0) && (y0 < HH);
            bool vy1 = (y0 >= -1) && (y0 < HH-1);
            bool vx0 = (x0 >= 0) && (x0 < WW);
            bool vx1 = (x0 >= -1) && (x0 < WW-1);
            int iy0 = min(max(y0, 0), HH-1), iy1 = min(max(y0+1, 0), HH-1);
            int ix0 = min(max(x0, 0), WW-1), ix1 = min(max(x0+1, 0), WW-1);
            pw_r.x = (vy0 && vx0) ? (1.f-wy)*(1.f-wx) : 0.f;
            pw_r.y = (vy0 && vx1) ? (1.f-wy)*wx       : 0.f;
            pw_r.z = (vy1 && vx0) ? wy*(1.f-wx)       : 0.f;
            pw_r.w = (vy1 && vx1) ? wy*wx             : 0.f;
            po_r.x = (iy0*WW + ix0)*CH*4;
            po_r.y = (iy0*WW + ix1)*CH*4;
            po_r.z = (iy1*WW + ix0)*CH*4;
            po_r.w = (iy1*WW + ix1)*CH*4;
        }

        // ---- gather 32 warp-local pixels: 8 chunks of 4 px (2 pairs) ----
#pragma unroll
        for (int ch_ = 0; ch_ < 8; ch_++) {
            float4 part[2];
            {   // pass 1: top corners
                float4 c00[2], c01[2];
#pragma unroll
                for (int i = 0; i < 2; i++) {
                    int j = ch_*4 + 2*i + psel;
                    int o0 = __shfl_sync(0xffffffffu, po_r.x, j);
                    int o1 = __shfl_sync(0xffffffffu, po_r.y, j);
                    c00[i] = *(const float4*)(xc + o0 + lc4);
                    c01[i] = *(const float4*)(xc + o1 + lc4);
                }
#pragma unroll
                for (int i = 0; i < 2; i++) {
                    int j = ch_*4 + 2*i + psel;
                    float w0_ = __shfl_sync(0xffffffffu, pw_r.x, j);
                    float w1_ = __shfl_sync(0xffffffffu, pw_r.y, j);
                    part[i].x = w0_*c00[i].x + w1_*c01[i].x;
                    part[i].y = w0_*c00[i].y + w1_*c01[i].y;
                    part[i].z = w0_*c00[i].z + w1_*c01[i].z;
                    part[i].w = w0_*c00[i].w + w1_*c01[i].w;
                }
            }
            {   // pass 2: bottom corners + convert + store
                float4 c10[2], c11[2];
#pragma unroll
                for (int i = 0; i < 2; i++) {
                    int j = ch_*4 + 2*i + psel;
                    int o2 = __shfl_sync(0xffffffffu, po_r.z, j);
                    int o3 = __shfl_sync(0xffffffffu, po_r.w, j);
                    c10[i] = *(const float4*)(xc + o2 + lc4);
                    c11[i] = *(const float4*)(xc + o3 + lc4);
                }
#pragma unroll
                for (int i = 0; i < 2; i++) {
                    int j = ch_*4 + 2*i + psel;
                    float w2_ = __shfl_sync(0xffffffffu, pw_r.z, j);
                    float w3_ = __shfl_sync(0xffffffffu, pw_r.w, j);
                    float4 r;
                    r.x = part[i].x + w2_*c10[i].x + w3_*c11[i].x;
                    r.y = part[i].y + w2_*c10[i].y + w3_*c11[i].y;
                    r.z = part[i].z + w2_*c10[i].z + w3_*c11[i].z;
                    r.w = part[i].w + w2_*c10[i].w + w3_*c11[i].w;
                    unsigned h2a = pk_bf16x2(r.x, r.y);
                    unsigned h2b = pk_bf16x2(r.z, r.w);
                    float hx = __uint_as_float(h2a << 16);
                    float hy = __uint_as_float(h2a & 0xFFFF0000u);
                    float hz = __uint_as_float(h2b << 16);
                    float hw_ = __uint_as_float(h2b & 0xFFFF0000u);
                    unsigned l2a = pk_bf16x2(r.x - hx, r.y - hy);
                    unsigned l2b = pk_bf16x2(r.z - hz, r.w - hw_);
                    int p = warp*32 + ch_*4 + 2*i + psel;
                    unsigned off = p*128 + ((((m >> 1) ^ (p & 7)) << 4) | (((2*m) & 3) << 2));
                    *(uint2*)(sm + SMA_HI + off) = make_uint2(h2a, h2b);
                    *(uint2*)(sm + SMA_LO + off) = make_uint2(l2a, l2b);
                }
            }
        }
        __syncwarp();

        // prefetch next position's offsets (coalesced; latency hidden by GEMM)
        if (k < K2-1)
            od = offT[(size_t)(k+1)*PIX + gpix];

        // ---- GEMM: m32 x n64 x k64, 3-term bf16 split; B loaded once per kt ----
        const uint4* bfH = &g_wfragH[k*512 + lane];
        const uint4* bfL = &g_wfragL[k*512 + lane];
#pragma unroll
        for (int kt = 0; kt < 4; kt++) {
            uint32_t aH0[4], aL0[4], aH1[4], aL1[4];
            int chunkk = 2*kt + a_cpar;
            uint32_t ad0 = sb + a_gr0*128 + ((chunkk ^ lrow) << 4);
            uint32_t ad1 = sb + a_gr1*128 + ((chunkk ^ lrow) << 4);
            ldsm4(aH0, ad0 + SMA_HI);
            ldsm4(aL0, ad0 + SMA_LO);
            ldsm4(aH1, ad1 + SMA_HI);
            ldsm4(aL1, ad1 + SMA_LO);
#pragma unroll
            for (int ng = 0; ng < 4; ng++) {
                uint4 BH = bfH[(kt*4 + ng)*32];
                uint4 BL = bfL[(kt*4 + ng)*32];
                mma16816(acc[0][2*ng],   aH0, BH.x, BH.y);
                mma16816(acc[0][2*ng],   aL0, BH.x, BH.y);
                mma16816(acc[0][2*ng],   aH0, BL.x, BL.y);
                mma16816(acc[0][2*ng+1], aH0, BH.z, BH.w);
                mma16816(acc[0][2*ng+1], aL0, BH.z, BH.w);
                mma16816(acc[0][2*ng+1], aH0, BL.z, BL.w);
                mma16816(acc[1][2*ng],   aH1, BH.x, BH.y);
                mma16816(acc[1][2*ng],   aL1, BH.x, BH.y);
                mma16816(acc[1][2*ng],   aH1, BL.x, BL.y);
                mma16816(acc[1][2*ng+1], aH1, BH.z, BH.w);
                mma16816(acc[1][2*ng+1], aL1, BH.z, BH.w);
                mma16816(acc[1][2*ng+1], aH1, BL.z, BL.w);
            }
        }
        __syncwarp();
    }

    // epilogue: write fragments to NCHW out (two m16 tiles)
    int r0 = lane >> 2;
    int cq = (lane & 3)*2;
    size_t obase = (size_t)b*OC*HW + (size_t)h*WW;
#pragma unroll
    for (int mt = 0; mt < 2; mt++) {
        int w0 = warp*32 + mt*16 + r0;
#pragma unroll
        for (int nt = 0; nt < 8; nt++) {
            int oc = nt*8 + cq;
            float bias0 = b_dcn[oc];
            float bias1 = b_dcn[oc+1];
            float* o0 = &out[obase + (size_t)oc*HW];
            float* o1 = &out[obase + (size_t)(oc+1)*HW];
            o0[w0]     = acc[mt][nt][0] + bias0;
            o1[w0]     = acc[mt][nt][1] + bias1;
            o0[w0 + 8] = acc[mt][nt][2] + bias0;
            o1[w0 + 8] = acc[mt][nt][3] + bias1;
        }
    }
}

// ============ launch ============
extern "C" void kernel_launch(void* const* d_in, const int* in_sizes, int n_in,
                              void* d_out, int out_size) {
    const float* x     = (const float*)d_in[0];
    const float* w_off = (const float*)d_in[1];
    const float* b_off = (const float*)d_in[2];
    const float* w_dcn = (const float*)d_in[3];
    const float* b_dcn = (const float*)d_in[4];
    float* out = (float*)d_out;

    cudaFuncSetAttribute(k_offconv, cudaFuncAttributeMaxDynamicSharedMemorySize, SMEM_OFF);
    cudaFuncSetAttribute(k_deform,  cudaFuncAttributeMaxDynamicSharedMemorySize, SMEM_DEF);

    k_transpose<<<dim3(WW/32, CH/32, BATCH*HH), dim3(32,8)>>>(x, w_off, w_dcn);
    k_offconv<<<BATCH*HH, 256, SMEM_OFF>>>(b_off);
    k_deform<<<PIX/128, 128, SMEM_DEF>>>(b_dcn, out);
}